// round 6
// baseline (speedup 1.0000x reference)
#include <cuda_runtime.h>
#include <math_constants.h>

// Problem constants (match reference)
#define POOLK 7
#define NUM_ROIS 300
#define FH 50
#define FW 50
#define FC 512

#define NBINS (NUM_ROIS * POOLK * POOLK)            // 14700
#define TOTAL_V4 (NUM_ROIS * POOLK * POOLK * (FC/4)) // 1,881,600 float4

// Scratch (no cudaMalloc allowed)
__device__ float g_fmax[FH * FW];
__device__ float g_bins[NBINS];

// ---------------------------------------------------------------------------
// Kernel A: fmax[h][w] = max_c feature_maps[h][w][c]
// One block per (h,w); 128 threads x float4 = 512 channels.
// ---------------------------------------------------------------------------
__global__ void __launch_bounds__(128) channel_max_kernel(const float* __restrict__ fm) {
    const int pos = blockIdx.x;               // 0 .. 2499
    const float4* __restrict__ p =
        reinterpret_cast<const float4*>(fm + (size_t)pos * FC);
    float4 v = p[threadIdx.x];
    float m = fmaxf(fmaxf(v.x, v.y), fmaxf(v.z, v.w));

    #pragma unroll
    for (int o = 16; o > 0; o >>= 1)
        m = fmaxf(m, __shfl_xor_sync(0xffffffffu, m, o));

    __shared__ float s[4];
    if ((threadIdx.x & 31) == 0) s[threadIdx.x >> 5] = m;
    __syncthreads();
    if (threadIdx.x == 0)
        g_fmax[pos] = fmaxf(fmaxf(s[0], s[1]), fmaxf(s[2], s[3]));
}

// ---------------------------------------------------------------------------
// Kernel B: one thread per (roi, bin). Fully-unrolled 5x5 predicated window
// max (window span provably <= 5 for rh,rw <= 26) so all loads pipeline into
// a single L2 round-trip.
// ---------------------------------------------------------------------------
__global__ void __launch_bounds__(128) bins_kernel(const float* __restrict__ rois) {
    const int idx = blockIdx.x * 128 + threadIdx.x;
    if (idx >= NBINS) return;

    const int roi = idx / (POOLK * POOLK);
    const int b   = idx - roi * (POOLK * POOLK);
    const int bi  = b / POOLK;
    const int bj  = b - bi * POOLK;

    const float* r = rois + (size_t)roi * 5;
    const int x1 = (int)(__ldg(r + 1) * 0.0625f);   // exact: /16, non-negative
    const int y1 = (int)(__ldg(r + 2) * 0.0625f);
    const int x2 = (int)(__ldg(r + 3) * 0.0625f);
    const int y2 = (int)(__ldg(r + 4) * 0.0625f);
    const int rh = y2 - y1 + 1;
    const int rw = x2 - x1 + 1;

    int hs = y1 + (bi * rh) / POOLK;
    int he = y1 + ((bi + 1) * rh + POOLK - 1) / POOLK;
    int ws = x1 + (bj * rw) / POOLK;
    int we = x1 + ((bj + 1) * rw + POOLK - 1) / POOLK;
    hs = min(max(hs, 0), FH);  he = min(max(he, 0), FH);
    ws = min(max(ws, 0), FW);  we = min(max(we, 0), FW);

    const int hh = he - hs;   // <= 5
    const int ww = we - ws;   // <= 5

    float m = -CUDART_INF_F;
    #pragma unroll
    for (int dr = 0; dr < 5; ++dr) {
        #pragma unroll
        for (int dc = 0; dc < 5; ++dc) {
            if (dr < hh && dc < ww)
                m = fmaxf(m, g_fmax[(hs + dr) * FW + (ws + dc)]);
        }
    }
    g_bins[idx] = m;
}

// ---------------------------------------------------------------------------
// Kernel C: pure streaming broadcast write. 1470 blocks x 256 threads,
// exactly 5 coalesced float4 stores per thread.
// ---------------------------------------------------------------------------
__global__ void __launch_bounds__(256) write_kernel(float* __restrict__ out) {
    const int tid    = blockIdx.x * 256 + threadIdx.x;
    const int stride = gridDim.x * 256;
    float4* __restrict__ o4 = reinterpret_cast<float4*>(out);
    #pragma unroll 5
    for (int v = tid; v < TOTAL_V4; v += stride) {
        const float f = g_bins[v >> 7];       // 128 float4 per bin; L1-resident
        o4[v] = make_float4(f, f, f, f);
    }
}

// ---------------------------------------------------------------------------
extern "C" void kernel_launch(void* const* d_in, const int* in_sizes, int n_in,
                              void* d_out, int out_size) {
    const float* rois = (const float*)d_in[0];
    const float* fm   = (const float*)d_in[1];
    if (n_in >= 2 && in_sizes[0] != NUM_ROIS * 5 && in_sizes[1] == NUM_ROIS * 5) {
        rois = (const float*)d_in[1];
        fm   = (const float*)d_in[0];
    }
    float* out = (float*)d_out;

    channel_max_kernel<<<FH * FW, 128>>>(fm);
    bins_kernel<<<(NBINS + 127) / 128, 128>>>(rois);
    write_kernel<<<1470, 256>>>(out);
}